// round 1
// baseline (speedup 1.0000x reference)
#include <cuda_runtime.h>

#define NN 100000
#define EE 1600000
#define KHOP 50

// ---------------- device scratch (static, no allocation) ----------------
__device__ float g_deg[NN];
__device__ float g_dis[NN];
__device__ int   g_cnt[NN];
__device__ int   g_off[NN + 1];
__device__ int   g_cur[NN];
__device__ int2  g_csc[EE];        // {src, bitcast(norm)}
__device__ float g_ha[NN * 32];
__device__ float g_hb[NN * 32];
__device__ float g_acc1[NN * 32];
__device__ float g_acc2[NN * 32];

// ---------------- setup kernels ----------------
__global__ void k_zero() {
    int i = blockIdx.x * blockDim.x + threadIdx.x;
    if (i < NN) { g_deg[i] = 0.f; g_cnt[i] = 0; }
}

__global__ void k_degcnt(const int* __restrict__ ei, const float* __restrict__ ew) {
    int e = blockIdx.x * blockDim.x + threadIdx.x;
    if (e < EE) {
        int c = ei[EE + e];
        atomicAdd(&g_deg[c], ew[e]);
        atomicAdd(&g_cnt[c], 1);
    }
}

__global__ void k_dis() {
    int i = blockIdx.x * blockDim.x + threadIdx.x;
    if (i < NN) {
        float d = g_deg[i];
        g_dis[i] = (d > 0.f) ? (1.0f / sqrtf(d)) : 0.f;
    }
}

// single-block exclusive scan over g_cnt -> g_off, g_cur (1024 threads)
__global__ void k_scan() {
    __shared__ int wsum[32];
    __shared__ int sh_carry;
    int tid = threadIdx.x, lane = tid & 31, wid = tid >> 5;
    if (tid == 0) sh_carry = 0;
    __syncthreads();
    for (int base = 0; base < NN; base += 1024) {
        int i = base + tid;
        int v = (i < NN) ? g_cnt[i] : 0;
        int x = v;
        #pragma unroll
        for (int d = 1; d < 32; d <<= 1) {
            int t = __shfl_up_sync(0xffffffffu, x, d);
            if (lane >= d) x += t;
        }
        if (lane == 31) wsum[wid] = x;
        __syncthreads();
        if (wid == 0) {
            int y = wsum[lane];
            #pragma unroll
            for (int d = 1; d < 32; d <<= 1) {
                int t = __shfl_up_sync(0xffffffffu, y, d);
                if (lane >= d) y += t;
            }
            wsum[lane] = y;
        }
        __syncthreads();
        int cb = sh_carry;
        int excl = cb + (wid ? wsum[wid - 1] : 0) + x - v;
        if (i < NN) { g_off[i] = excl; g_cur[i] = excl; }
        __syncthreads();
        if (tid == 0) sh_carry = cb + wsum[31];
        __syncthreads();
    }
    if (tid == 0) g_off[NN] = sh_carry;
}

__global__ void k_scatter(const int* __restrict__ ei, const float* __restrict__ ew) {
    int e = blockIdx.x * blockDim.x + threadIdx.x;
    if (e < EE) {
        int r = ei[e], c = ei[EE + e];
        float nrm = g_dis[r] * ew[e] * g_dis[c];
        int p = atomicAdd(&g_cur[c], 1);
        g_csc[p] = make_int2(r, __float_as_int(nrm));
    }
}

// ---------------- layer 1 (fin=2) ----------------
__global__ void k_init1(const float* __restrict__ c, const int* __restrict__ ip,
                        const float* __restrict__ W, const float* __restrict__ b) {
    __shared__ float sW[30];
    __shared__ float sb[15];
    if (threadIdx.x < 30) sW[threadIdx.x] = W[threadIdx.x];
    if (threadIdx.x < 15) sb[threadIdx.x] = b[threadIdx.x];
    __syncthreads();
    int n = blockIdx.x * blockDim.x + threadIdx.x;
    if (n >= NN) return;
    int iv = ip[0];
    float cv = (n == iv) ? 1.f : 0.f;
    float cc = c[n];
    ((float2*)g_ha)[n] = make_float2(cv, cc);
    float o[16];
    #pragma unroll
    for (int j = 0; j < 15; j++) o[j] = sb[j] + cv * sW[j] + cc * sW[15 + j];
    o[15] = 0.f;
    float4* ap = (float4*)(g_acc1 + n * 16);
    ap[0] = *(float4*)(o + 0); ap[1] = *(float4*)(o + 4);
    ap[2] = *(float4*)(o + 8); ap[3] = *(float4*)(o + 12);
}

__global__ void k_spmm1(int pp, const float* __restrict__ Wk) {
    __shared__ float sW[30];
    if (threadIdx.x < 30) sW[threadIdx.x] = Wk[threadIdx.x];
    __syncthreads();
    int n = blockIdx.x * blockDim.x + threadIdx.x;
    if (n >= NN) return;
    const float2* hc = (const float2*)(pp ? g_hb : g_ha);
    float2* hn = (float2*)(pp ? g_ha : g_hb);
    int s = g_off[n], e = g_off[n + 1];
    float ax = 0.f, ay = 0.f;
    int t = s;
    for (; t + 4 <= e; t += 4) {
        int2 a0 = g_csc[t], a1 = g_csc[t + 1], a2 = g_csc[t + 2], a3 = g_csc[t + 3];
        float2 v0 = hc[a0.x], v1 = hc[a1.x], v2 = hc[a2.x], v3 = hc[a3.x];
        float w0 = __int_as_float(a0.y), w1 = __int_as_float(a1.y);
        float w2 = __int_as_float(a2.y), w3 = __int_as_float(a3.y);
        ax = fmaf(w0, v0.x, ax); ay = fmaf(w0, v0.y, ay);
        ax = fmaf(w1, v1.x, ax); ay = fmaf(w1, v1.y, ay);
        ax = fmaf(w2, v2.x, ax); ay = fmaf(w2, v2.y, ay);
        ax = fmaf(w3, v3.x, ax); ay = fmaf(w3, v3.y, ay);
    }
    for (; t < e; t++) {
        int2 a = g_csc[t];
        float2 v = hc[a.x];
        float w = __int_as_float(a.y);
        ax = fmaf(w, v.x, ax); ay = fmaf(w, v.y, ay);
    }
    hn[n] = make_float2(ax, ay);
    float o[16];
    float4* ap = (float4*)(g_acc1 + n * 16);
    *(float4*)(o + 0) = ap[0]; *(float4*)(o + 4) = ap[1];
    *(float4*)(o + 8) = ap[2]; *(float4*)(o + 12) = ap[3];
    #pragma unroll
    for (int j = 0; j < 15; j++) o[j] += ax * sW[j] + ay * sW[15 + j];
    ap[0] = *(float4*)(o + 0); ap[1] = *(float4*)(o + 4);
    ap[2] = *(float4*)(o + 8); ap[3] = *(float4*)(o + 12);
}

// ---------------- generic fused SpMM + matmul-accumulate ----------------
// LP float4-lanes per node (FP = 4*LP padded fin), FIN real fin, FOUT outputs,
// FOUTP padded out stride. accsel: 0 -> g_acc1, 1 -> g_acc2.
template <int LP, int FIN, int FOUT, int FOUTP>
__global__ void k_spmm(int pp, const float* __restrict__ Wk, int accsel) {
    constexpr int NPB = 256 / LP;
    constexpr int FP = LP * 4;
    __shared__ float sm[NPB][FP];
    __shared__ float sW[FIN * FOUT];
    for (int idx = threadIdx.x; idx < FIN * FOUT; idx += 256) sW[idx] = Wk[idx];
    const float* hc = pp ? g_hb : g_ha;
    float* hn = pp ? g_ha : g_hb;
    float* A = accsel ? g_acc2 : g_acc1;
    int g = threadIdx.x / LP;
    int l = threadIdx.x % LP;
    int n = blockIdx.x * NPB + g;
    float4 acc = make_float4(0.f, 0.f, 0.f, 0.f);
    if (n < NN) {
        int s = g_off[n], e = g_off[n + 1];
        const float4* h4 = (const float4*)hc;
        int t = s;
        for (; t + 4 <= e; t += 4) {
            int2 a0 = g_csc[t], a1 = g_csc[t + 1], a2 = g_csc[t + 2], a3 = g_csc[t + 3];
            float4 v0 = h4[a0.x * LP + l];
            float4 v1 = h4[a1.x * LP + l];
            float4 v2 = h4[a2.x * LP + l];
            float4 v3 = h4[a3.x * LP + l];
            float w0 = __int_as_float(a0.y), w1 = __int_as_float(a1.y);
            float w2 = __int_as_float(a2.y), w3 = __int_as_float(a3.y);
            acc.x = fmaf(w0, v0.x, acc.x); acc.y = fmaf(w0, v0.y, acc.y);
            acc.z = fmaf(w0, v0.z, acc.z); acc.w = fmaf(w0, v0.w, acc.w);
            acc.x = fmaf(w1, v1.x, acc.x); acc.y = fmaf(w1, v1.y, acc.y);
            acc.z = fmaf(w1, v1.z, acc.z); acc.w = fmaf(w1, v1.w, acc.w);
            acc.x = fmaf(w2, v2.x, acc.x); acc.y = fmaf(w2, v2.y, acc.y);
            acc.z = fmaf(w2, v2.z, acc.z); acc.w = fmaf(w2, v2.w, acc.w);
            acc.x = fmaf(w3, v3.x, acc.x); acc.y = fmaf(w3, v3.y, acc.y);
            acc.z = fmaf(w3, v3.z, acc.z); acc.w = fmaf(w3, v3.w, acc.w);
        }
        for (; t < e; t++) {
            int2 a = g_csc[t];
            float4 v = h4[a.x * LP + l];
            float w = __int_as_float(a.y);
            acc.x = fmaf(w, v.x, acc.x); acc.y = fmaf(w, v.y, acc.y);
            acc.z = fmaf(w, v.z, acc.z); acc.w = fmaf(w, v.w, acc.w);
        }
        ((float4*)hn)[n * LP + l] = acc;
    }
    *(float4*)&sm[g][l * 4] = acc;
    __syncthreads();
    for (int idx = threadIdx.x; idx < NPB * FOUT; idx += 256) {
        int nl = idx / FOUT, j = idx - nl * FOUT;
        int n2 = blockIdx.x * NPB + nl;
        if (n2 < NN) {
            float sum = 0.f;
            #pragma unroll
            for (int f = 0; f < FIN; f++) sum = fmaf(sm[nl][f], sW[f * FOUT + j], sum);
            A[n2 * FOUTP + j] += sum;
        }
    }
}

// ---------------- transitions (relu + out0 of next layer) ----------------
__global__ void k_trans12(const float* __restrict__ W, const float* __restrict__ b) {
    __shared__ float sW[450];
    __shared__ float sb[30];
    for (int idx = threadIdx.x; idx < 450; idx += 256) sW[idx] = W[idx];
    if (threadIdx.x < 30) sb[threadIdx.x] = b[threadIdx.x];
    __syncthreads();
    int n = blockIdx.x * blockDim.x + threadIdx.x;
    if (n >= NN) return;
    float v[16];
    const float4* ap = (const float4*)(g_acc1 + n * 16);
    *(float4*)(v + 0) = ap[0]; *(float4*)(v + 4) = ap[1];
    *(float4*)(v + 8) = ap[2]; *(float4*)(v + 12) = ap[3];
    #pragma unroll
    for (int f = 0; f < 15; f++) v[f] = fmaxf(v[f], 0.f);
    v[15] = 0.f;
    float4* hp = (float4*)(g_ha + n * 16);
    hp[0] = *(float4*)(v + 0); hp[1] = *(float4*)(v + 4);
    hp[2] = *(float4*)(v + 8); hp[3] = *(float4*)(v + 12);
    float o[32];
    #pragma unroll
    for (int j = 0; j < 30; j++) o[j] = sb[j];
    o[30] = 0.f; o[31] = 0.f;
    #pragma unroll
    for (int f = 0; f < 15; f++) {
        float vf = v[f];
        #pragma unroll
        for (int j = 0; j < 30; j++) o[j] = fmaf(vf, sW[f * 30 + j], o[j]);
    }
    float4* op = (float4*)(g_acc2 + n * 32);
    #pragma unroll
    for (int q = 0; q < 8; q++) op[q] = *(float4*)(o + 4 * q);
}

__global__ void k_trans23(const float* __restrict__ W, const float* __restrict__ b) {
    __shared__ float sW[450];
    __shared__ float sb[15];
    for (int idx = threadIdx.x; idx < 450; idx += 256) sW[idx] = W[idx];
    if (threadIdx.x < 15) sb[threadIdx.x] = b[threadIdx.x];
    __syncthreads();
    int n = blockIdx.x * blockDim.x + threadIdx.x;
    if (n >= NN) return;
    float v[32];
    const float4* ap = (const float4*)(g_acc2 + n * 32);
    #pragma unroll
    for (int q = 0; q < 8; q++) *(float4*)(v + 4 * q) = ap[q];
    #pragma unroll
    for (int f = 0; f < 30; f++) v[f] = fmaxf(v[f], 0.f);
    v[30] = 0.f; v[31] = 0.f;
    float4* hp = (float4*)(g_ha + n * 32);
    #pragma unroll
    for (int q = 0; q < 8; q++) hp[q] = *(float4*)(v + 4 * q);
    float o[16];
    #pragma unroll
    for (int j = 0; j < 15; j++) o[j] = sb[j];
    o[15] = 0.f;
    #pragma unroll
    for (int f = 0; f < 30; f++) {
        float vf = v[f];
        #pragma unroll
        for (int j = 0; j < 15; j++) o[j] = fmaf(vf, sW[f * 15 + j], o[j]);
    }
    float4* op = (float4*)(g_acc1 + n * 16);
    #pragma unroll
    for (int q = 0; q < 4; q++) op[q] = *(float4*)(o + 4 * q);
}

__global__ void k_trans34(const float* __restrict__ W, const float* __restrict__ b) {
    __shared__ float sW[15];
    __shared__ float sb0;
    if (threadIdx.x < 15) sW[threadIdx.x] = W[threadIdx.x];
    if (threadIdx.x == 0) sb0 = b[0];
    __syncthreads();
    int n = blockIdx.x * blockDim.x + threadIdx.x;
    if (n >= NN) return;
    float v[16];
    const float4* ap = (const float4*)(g_acc1 + n * 16);
    *(float4*)(v + 0) = ap[0]; *(float4*)(v + 4) = ap[1];
    *(float4*)(v + 8) = ap[2]; *(float4*)(v + 12) = ap[3];
    #pragma unroll
    for (int f = 0; f < 15; f++) v[f] = fmaxf(v[f], 0.f);
    v[15] = 0.f;
    float4* hp = (float4*)(g_ha + n * 16);
    hp[0] = *(float4*)(v + 0); hp[1] = *(float4*)(v + 4);
    hp[2] = *(float4*)(v + 8); hp[3] = *(float4*)(v + 12);
    float o = sb0;
    #pragma unroll
    for (int f = 0; f < 15; f++) o = fmaf(v[f], sW[f], o);
    g_acc2[n] = o;
}

__global__ void k_final(float* __restrict__ out) {
    int n = blockIdx.x * blockDim.x + threadIdx.x;
    if (n < NN) out[n] = fmaxf(g_acc2[n], 0.f);
}

// ---------------- host launch ----------------
static inline int div_up(int a, int b) { return (a + b - 1) / b; }

extern "C" void kernel_launch(void* const* d_in, const int* in_sizes, int n_in,
                              void* d_out, int out_size) {
    const int*   ei = (const int*)d_in[0];    // [2, E]
    const float* ew = (const float*)d_in[1];  // [E]
    const float* c  = (const float*)d_in[2];  // [N]
    const int*   ip = (const int*)d_in[3];    // scalar i
    const float* W1 = (const float*)d_in[4];
    const float* b1 = (const float*)d_in[5];
    const float* W2 = (const float*)d_in[6];
    const float* b2 = (const float*)d_in[7];
    const float* W3 = (const float*)d_in[8];
    const float* b3 = (const float*)d_in[9];
    const float* W4 = (const float*)d_in[10];
    const float* b4 = (const float*)d_in[11];
    float* out = (float*)d_out;

    int nb = div_up(NN, 256);
    int eb = div_up(EE, 256);

    // graph preprocessing (once per launch)
    k_zero<<<nb, 256>>>();
    k_degcnt<<<eb, 256>>>(ei, ew);
    k_dis<<<nb, 256>>>();
    k_scan<<<1, 1024>>>();
    k_scatter<<<eb, 256>>>(ei, ew);

    // layer 1: fin=2, fout=15, acc1
    k_init1<<<nb, 256>>>(c, ip, W1, b1);
    int pp = 0;
    for (int k = 1; k <= KHOP; k++) {
        k_spmm1<<<nb, 256>>>(pp, W1 + k * 2 * 15);
        pp ^= 1;
    }

    // layer 2: fin=15 (pad16, LP=4), fout=30 (pad32), acc2
    k_trans12<<<nb, 256>>>(W2, b2);
    pp = 0;
    for (int k = 1; k <= KHOP; k++) {
        k_spmm<4, 15, 30, 32><<<div_up(NN, 64), 256>>>(pp, W2 + k * 450, 1);
        pp ^= 1;
    }

    // layer 3: fin=30 (pad32, LP=8), fout=15 (pad16), acc1
    k_trans23<<<nb, 256>>>(W3, b3);
    pp = 0;
    for (int k = 1; k <= KHOP; k++) {
        k_spmm<8, 30, 15, 16><<<div_up(NN, 32), 256>>>(pp, W3 + k * 450, 0);
        pp ^= 1;
    }

    // layer 4: fin=15 (pad16, LP=4), fout=1, acc2
    k_trans34<<<nb, 256>>>(W4, b4);
    pp = 0;
    for (int k = 1; k <= KHOP; k++) {
        k_spmm<4, 15, 1, 1><<<div_up(NN, 64), 256>>>(pp, W4 + k * 15, 1);
        pp ^= 1;
    }

    k_final<<<nb, 256>>>(out);
}

// round 2
// speedup vs baseline: 1.1691x; 1.1691x over previous
#include <cuda_runtime.h>

#define NN 100000
#define EE 1600000
#define KHOP 50
#define SCAN_BS 1024
#define NBLK_SCAN ((NN + SCAN_BS - 1) / SCAN_BS)

// ---------------- device scratch (static, no allocation) ----------------
__device__ float g_deg[NN];
__device__ float g_dis[NN];
__device__ int   g_cnt[NN];
__device__ int   g_off[NN + 1];
__device__ int   g_cur[NN];
__device__ int   g_bsum[NBLK_SCAN];
__device__ int   g_boff[NBLK_SCAN];
__device__ int2  g_csc[EE];        // {src, bitcast(norm)}
__device__ float g_ha[NN * 32];
__device__ float g_hb[NN * 32];
__device__ float g_acc1[NN * 32];
__device__ float g_acc2[NN * 32];
__device__ float g_x3[NN * 32];
__device__ float g_z4[(KHOP + 1) * NN];
__device__ float g_t4a[NN];
__device__ float g_t4b[NN];

// ---------------- setup kernels ----------------
__global__ void k_zero() {
    int i = blockIdx.x * blockDim.x + threadIdx.x;
    if (i < NN) { g_deg[i] = 0.f; g_cnt[i] = 0; }
}

__global__ void k_degcnt(const int* __restrict__ ei, const float* __restrict__ ew) {
    int e = blockIdx.x * blockDim.x + threadIdx.x;
    if (e < EE) {
        int c = ei[EE + e];
        atomicAdd(&g_deg[c], ew[e]);
        atomicAdd(&g_cnt[c], 1);
    }
}

__global__ void k_dis() {
    int i = blockIdx.x * blockDim.x + threadIdx.x;
    if (i < NN) {
        float d = g_deg[i];
        g_dis[i] = (d > 0.f) ? (1.0f / sqrtf(d)) : 0.f;
    }
}

__global__ void k_bsum() {
    __shared__ int ws[32];
    int tid = threadIdx.x, lane = tid & 31, wid = tid >> 5;
    int i = blockIdx.x * SCAN_BS + tid;
    int v = (i < NN) ? g_cnt[i] : 0;
    #pragma unroll
    for (int d = 16; d >= 1; d >>= 1) v += __shfl_down_sync(0xffffffffu, v, d);
    if (lane == 0) ws[wid] = v;
    __syncthreads();
    if (wid == 0) {
        int y = ws[lane];
        #pragma unroll
        for (int d = 16; d >= 1; d >>= 1) y += __shfl_down_sync(0xffffffffu, y, d);
        if (lane == 0) g_bsum[blockIdx.x] = y;
    }
}

__global__ void k_bscan() {
    __shared__ int ws[4];
    int tid = threadIdx.x, lane = tid & 31, wid = tid >> 5;
    int v = (tid < NBLK_SCAN) ? g_bsum[tid] : 0;
    int x = v;
    #pragma unroll
    for (int d = 1; d < 32; d <<= 1) {
        int t = __shfl_up_sync(0xffffffffu, x, d);
        if (lane >= d) x += t;
    }
    if (lane == 31) ws[wid] = x;
    __syncthreads();
    int base = 0;
    for (int w = 0; w < wid; w++) base += ws[w];
    if (tid < NBLK_SCAN) g_boff[tid] = base + x - v;
}

__global__ void k_scan2() {
    __shared__ int ws[32];
    int tid = threadIdx.x, lane = tid & 31, wid = tid >> 5;
    int i = blockIdx.x * SCAN_BS + tid;
    int v = (i < NN) ? g_cnt[i] : 0;
    int x = v;
    #pragma unroll
    for (int d = 1; d < 32; d <<= 1) {
        int t = __shfl_up_sync(0xffffffffu, x, d);
        if (lane >= d) x += t;
    }
    if (lane == 31) ws[wid] = x;
    __syncthreads();
    if (wid == 0) {
        int y = ws[lane];
        #pragma unroll
        for (int d = 1; d < 32; d <<= 1) {
            int t = __shfl_up_sync(0xffffffffu, y, d);
            if (lane >= d) y += t;
        }
        ws[lane] = y;
    }
    __syncthreads();
    int excl = g_boff[blockIdx.x] + (wid ? ws[wid - 1] : 0) + x - v;
    if (i < NN) {
        g_off[i] = excl;
        g_cur[i] = excl;
        if (i == NN - 1) g_off[NN] = excl + v;
    }
}

__global__ void k_scatter(const int* __restrict__ ei, const float* __restrict__ ew) {
    int e = blockIdx.x * blockDim.x + threadIdx.x;
    if (e < EE) {
        int r = ei[e], c = ei[EE + e];
        float nrm = g_dis[r] * ew[e] * g_dis[c];
        int p = atomicAdd(&g_cur[c], 1);
        g_csc[p] = make_int2(r, __float_as_int(nrm));
    }
}

// ---------------- layer 1 (forward, fin=2, fout=15, acc1) ----------------
__global__ void k_init1(const float* __restrict__ c, const int* __restrict__ ip,
                        const float* __restrict__ W, const float* __restrict__ b) {
    __shared__ float sW[30];
    __shared__ float sb[15];
    if (threadIdx.x < 30) sW[threadIdx.x] = W[threadIdx.x];
    if (threadIdx.x < 15) sb[threadIdx.x] = b[threadIdx.x];
    __syncthreads();
    int n = blockIdx.x * blockDim.x + threadIdx.x;
    if (n >= NN) return;
    int iv = ip[0];
    float cv = (n == iv) ? 1.f : 0.f;
    float cc = c[n];
    ((float2*)g_ha)[n] = make_float2(cv, cc);
    float o[16];
    #pragma unroll
    for (int j = 0; j < 15; j++) o[j] = sb[j] + cv * sW[j] + cc * sW[15 + j];
    o[15] = 0.f;
    float4* ap = (float4*)(g_acc1 + n * 16);
    ap[0] = *(float4*)(o + 0); ap[1] = *(float4*)(o + 4);
    ap[2] = *(float4*)(o + 8); ap[3] = *(float4*)(o + 12);
}

__global__ void k_spmm1(int pp, const float* __restrict__ Wk) {
    __shared__ float sW[30];
    if (threadIdx.x < 30) sW[threadIdx.x] = Wk[threadIdx.x];
    __syncthreads();
    int n = blockIdx.x * blockDim.x + threadIdx.x;
    if (n >= NN) return;
    const float2* hc = (const float2*)(pp ? g_hb : g_ha);
    float2* hn = (float2*)(pp ? g_ha : g_hb);
    int s = g_off[n], e = g_off[n + 1];
    float ax = 0.f, ay = 0.f;
    int t = s;
    for (; t + 4 <= e; t += 4) {
        int2 a0 = g_csc[t], a1 = g_csc[t + 1], a2 = g_csc[t + 2], a3 = g_csc[t + 3];
        float2 v0 = hc[a0.x], v1 = hc[a1.x], v2 = hc[a2.x], v3 = hc[a3.x];
        float w0 = __int_as_float(a0.y), w1 = __int_as_float(a1.y);
        float w2 = __int_as_float(a2.y), w3 = __int_as_float(a3.y);
        ax = fmaf(w0, v0.x, ax); ay = fmaf(w0, v0.y, ay);
        ax = fmaf(w1, v1.x, ax); ay = fmaf(w1, v1.y, ay);
        ax = fmaf(w2, v2.x, ax); ay = fmaf(w2, v2.y, ay);
        ax = fmaf(w3, v3.x, ax); ay = fmaf(w3, v3.y, ay);
    }
    for (; t < e; t++) {
        int2 a = g_csc[t];
        float2 v = hc[a.x];
        float w = __int_as_float(a.y);
        ax = fmaf(w, v.x, ax); ay = fmaf(w, v.y, ay);
    }
    hn[n] = make_float2(ax, ay);
    float o[16];
    float4* ap = (float4*)(g_acc1 + n * 16);
    *(float4*)(o + 0) = ap[0]; *(float4*)(o + 4) = ap[1];
    *(float4*)(o + 8) = ap[2]; *(float4*)(o + 12) = ap[3];
    #pragma unroll
    for (int j = 0; j < 15; j++) o[j] += ax * sW[j] + ay * sW[15 + j];
    ap[0] = *(float4*)(o + 0); ap[1] = *(float4*)(o + 4);
    ap[2] = *(float4*)(o + 8); ap[3] = *(float4*)(o + 12);
}

// ---------------- layer 2 (forward, fin=15 pad16 LP=4, fout=30 pad32) -------
__global__ void k_spmm2(int pp, const float* __restrict__ Wk) {
    constexpr int LP = 4, NPB = 64, FIN = 15, FOUT = 30, FOUTP = 32;
    __shared__ float sm[NPB][16];
    __shared__ float sW[FIN * FOUT];
    for (int idx = threadIdx.x; idx < FIN * FOUT; idx += 256) sW[idx] = Wk[idx];
    const float* hc = pp ? g_hb : g_ha;
    float* hn = pp ? g_ha : g_hb;
    int g = threadIdx.x / LP;
    int l = threadIdx.x % LP;
    int n = blockIdx.x * NPB + g;
    float4 acc = make_float4(0.f, 0.f, 0.f, 0.f);
    if (n < NN) {
        int s = g_off[n], e = g_off[n + 1];
        const float4* h4 = (const float4*)hc;
        int t = s;
        for (; t + 4 <= e; t += 4) {
            int2 a0 = g_csc[t], a1 = g_csc[t + 1], a2 = g_csc[t + 2], a3 = g_csc[t + 3];
            float4 v0 = h4[a0.x * LP + l];
            float4 v1 = h4[a1.x * LP + l];
            float4 v2 = h4[a2.x * LP + l];
            float4 v3 = h4[a3.x * LP + l];
            float w0 = __int_as_float(a0.y), w1 = __int_as_float(a1.y);
            float w2 = __int_as_float(a2.y), w3 = __int_as_float(a3.y);
            acc.x = fmaf(w0, v0.x, acc.x); acc.y = fmaf(w0, v0.y, acc.y);
            acc.z = fmaf(w0, v0.z, acc.z); acc.w = fmaf(w0, v0.w, acc.w);
            acc.x = fmaf(w1, v1.x, acc.x); acc.y = fmaf(w1, v1.y, acc.y);
            acc.z = fmaf(w1, v1.z, acc.z); acc.w = fmaf(w1, v1.w, acc.w);
            acc.x = fmaf(w2, v2.x, acc.x); acc.y = fmaf(w2, v2.y, acc.y);
            acc.z = fmaf(w2, v2.z, acc.z); acc.w = fmaf(w2, v2.w, acc.w);
            acc.x = fmaf(w3, v3.x, acc.x); acc.y = fmaf(w3, v3.y, acc.y);
            acc.z = fmaf(w3, v3.z, acc.z); acc.w = fmaf(w3, v3.w, acc.w);
        }
        for (; t < e; t++) {
            int2 a = g_csc[t];
            float4 v = h4[a.x * LP + l];
            float w = __int_as_float(a.y);
            acc.x = fmaf(w, v.x, acc.x); acc.y = fmaf(w, v.y, acc.y);
            acc.z = fmaf(w, v.z, acc.z); acc.w = fmaf(w, v.w, acc.w);
        }
        ((float4*)hn)[n * LP + l] = acc;
    }
    *(float4*)&sm[g][l * 4] = acc;
    __syncthreads();
    for (int idx = threadIdx.x; idx < NPB * FOUT; idx += 256) {
        int nl = idx / FOUT, j = idx - nl * FOUT;
        int n2 = blockIdx.x * NPB + nl;
        if (n2 < NN) {
            float sum = 0.f;
            #pragma unroll
            for (int f = 0; f < FIN; f++) sum = fmaf(sm[nl][f], sW[f * FOUT + j], sum);
            g_acc2[n2 * FOUTP + j] += sum;
        }
    }
}

// ---------------- transition 1->2 ----------------
__global__ void k_trans12(const float* __restrict__ W, const float* __restrict__ b) {
    __shared__ float sW[450];
    __shared__ float sb[30];
    for (int idx = threadIdx.x; idx < 450; idx += 256) sW[idx] = W[idx];
    if (threadIdx.x < 30) sb[threadIdx.x] = b[threadIdx.x];
    __syncthreads();
    int n = blockIdx.x * blockDim.x + threadIdx.x;
    if (n >= NN) return;
    float v[16];
    const float4* ap = (const float4*)(g_acc1 + n * 16);
    *(float4*)(v + 0) = ap[0]; *(float4*)(v + 4) = ap[1];
    *(float4*)(v + 8) = ap[2]; *(float4*)(v + 12) = ap[3];
    #pragma unroll
    for (int f = 0; f < 15; f++) v[f] = fmaxf(v[f], 0.f);
    v[15] = 0.f;
    float4* hp = (float4*)(g_ha + n * 16);
    hp[0] = *(float4*)(v + 0); hp[1] = *(float4*)(v + 4);
    hp[2] = *(float4*)(v + 8); hp[3] = *(float4*)(v + 12);
    float o[32];
    #pragma unroll
    for (int j = 0; j < 30; j++) o[j] = sb[j];
    o[30] = 0.f; o[31] = 0.f;
    #pragma unroll
    for (int f = 0; f < 15; f++) {
        float vf = v[f];
        #pragma unroll
        for (int j = 0; j < 30; j++) o[j] = fmaf(vf, sW[f * 30 + j], o[j]);
    }
    float4* op = (float4*)(g_acc2 + n * 32);
    #pragma unroll
    for (int q = 0; q < 8; q++) op[q] = *(float4*)(o + 4 * q);
}

// ---- transition 2->3 (Horner init): x3 = relu(acc2); t_K = x3 W3[K] --------
__global__ void k_trans23(const float* __restrict__ WK) {
    __shared__ float sW[450];
    for (int idx = threadIdx.x; idx < 450; idx += 256) sW[idx] = WK[idx];
    __syncthreads();
    int n = blockIdx.x * blockDim.x + threadIdx.x;
    if (n >= NN) return;
    float v[32];
    const float4* ap = (const float4*)(g_acc2 + n * 32);
    #pragma unroll
    for (int q = 0; q < 8; q++) *(float4*)(v + 4 * q) = ap[q];
    #pragma unroll
    for (int f = 0; f < 30; f++) v[f] = fmaxf(v[f], 0.f);
    v[30] = 0.f; v[31] = 0.f;
    float4* xp = (float4*)(g_x3 + n * 32);
    #pragma unroll
    for (int q = 0; q < 8; q++) xp[q] = *(float4*)(v + 4 * q);
    float o[16];
    #pragma unroll
    for (int j = 0; j < 16; j++) o[j] = 0.f;
    #pragma unroll
    for (int f = 0; f < 30; f++) {
        float vf = v[f];
        #pragma unroll
        for (int j = 0; j < 15; j++) o[j] = fmaf(vf, sW[f * 15 + j], o[j]);
    }
    float4* tp = (float4*)(g_ha + n * 16);
    #pragma unroll
    for (int q = 0; q < 4; q++) tp[q] = *(float4*)(o + 4 * q);
}

// ------- layer 3 Horner hop: t_new = x3 W3_k [+ b3 if last] + A t_old -------
__global__ void k_hop3(int pp, const float* __restrict__ Wk, int addb,
                       const float* __restrict__ b) {
    __shared__ float sW[32 * 16];   // rows 30,31 and col 15 zero-padded
    __shared__ float sb[16];
    int tid = threadIdx.x;
    for (int idx = tid; idx < 512; idx += 256) {
        int f = idx >> 4, j = idx & 15;
        sW[idx] = (f < 30 && j < 15) ? Wk[f * 15 + j] : 0.f;
    }
    if (tid < 16) sb[tid] = (addb && tid < 15) ? b[tid] : 0.f;
    __syncthreads();
    int g = tid >> 2, l = tid & 3;
    int n = blockIdx.x * 64 + g;
    if (n >= NN) return;
    const float4* t_old = (const float4*)(pp ? g_hb : g_ha);
    float4* t_new = (float4*)(pp ? g_ha : g_hb);
    int s = g_off[n], e = g_off[n + 1];
    float4 acc = make_float4(0.f, 0.f, 0.f, 0.f);
    int t = s;
    for (; t + 4 <= e; t += 4) {
        int2 a0 = g_csc[t], a1 = g_csc[t + 1], a2 = g_csc[t + 2], a3 = g_csc[t + 3];
        float4 v0 = t_old[a0.x * 4 + l];
        float4 v1 = t_old[a1.x * 4 + l];
        float4 v2 = t_old[a2.x * 4 + l];
        float4 v3 = t_old[a3.x * 4 + l];
        float w0 = __int_as_float(a0.y), w1 = __int_as_float(a1.y);
        float w2 = __int_as_float(a2.y), w3 = __int_as_float(a3.y);
        acc.x = fmaf(w0, v0.x, acc.x); acc.y = fmaf(w0, v0.y, acc.y);
        acc.z = fmaf(w0, v0.z, acc.z); acc.w = fmaf(w0, v0.w, acc.w);
        acc.x = fmaf(w1, v1.x, acc.x); acc.y = fmaf(w1, v1.y, acc.y);
        acc.z = fmaf(w1, v1.z, acc.z); acc.w = fmaf(w1, v1.w, acc.w);
        acc.x = fmaf(w2, v2.x, acc.x); acc.y = fmaf(w2, v2.y, acc.y);
        acc.z = fmaf(w2, v2.z, acc.z); acc.w = fmaf(w2, v2.w, acc.w);
        acc.x = fmaf(w3, v3.x, acc.x); acc.y = fmaf(w3, v3.y, acc.y);
        acc.z = fmaf(w3, v3.z, acc.z); acc.w = fmaf(w3, v3.w, acc.w);
    }
    for (; t < e; t++) {
        int2 a = g_csc[t];
        float4 v = t_old[a.x * 4 + l];
        float w = __int_as_float(a.y);
        acc.x = fmaf(w, v.x, acc.x); acc.y = fmaf(w, v.y, acc.y);
        acc.z = fmaf(w, v.z, acc.z); acc.w = fmaf(w, v.w, acc.w);
    }
    int j0 = l * 4;
    float zx = sb[j0], zy = sb[j0 + 1], zz = sb[j0 + 2], zw = sb[j0 + 3];
    const float4* xr = (const float4*)(g_x3 + n * 32);
    #pragma unroll
    for (int q = 0; q < 8; q++) {
        float4 xq = xr[q];
        const float* w0 = &sW[(4 * q) * 16 + j0];
        const float* w1 = &sW[(4 * q + 1) * 16 + j0];
        const float* w2 = &sW[(4 * q + 2) * 16 + j0];
        const float* w3 = &sW[(4 * q + 3) * 16 + j0];
        zx = fmaf(xq.x, w0[0], zx); zy = fmaf(xq.x, w0[1], zy);
        zz = fmaf(xq.x, w0[2], zz); zw = fmaf(xq.x, w0[3], zw);
        zx = fmaf(xq.y, w1[0], zx); zy = fmaf(xq.y, w1[1], zy);
        zz = fmaf(xq.y, w1[2], zz); zw = fmaf(xq.y, w1[3], zw);
        zx = fmaf(xq.z, w2[0], zx); zy = fmaf(xq.z, w2[1], zy);
        zz = fmaf(xq.z, w2[2], zz); zw = fmaf(xq.z, w2[3], zw);
        zx = fmaf(xq.w, w3[0], zx); zy = fmaf(xq.w, w3[1], zy);
        zz = fmaf(xq.w, w3[2], zz); zw = fmaf(xq.w, w3[3], zw);
    }
    acc.x += zx; acc.y += zy; acc.z += zz; acc.w += zw;
    t_new[n * 4 + l] = acc;
}

// ---- transition 3->4: x4 = relu(t3_0); z4[k][n] = x4 . W4_k (+b4 at k=0) ---
__global__ void k_z4(const float* __restrict__ W4, const float* __restrict__ b4) {
    __shared__ float sW[(KHOP + 1) * 15];
    __shared__ float sb0;
    for (int idx = threadIdx.x; idx < (KHOP + 1) * 15; idx += 256) sW[idx] = W4[idx];
    if (threadIdx.x == 0) sb0 = b4[0];
    __syncthreads();
    int n = blockIdx.x * blockDim.x + threadIdx.x;
    if (n >= NN) return;
    float v[16];
    const float4* tp = (const float4*)(g_ha + n * 16);  // 50 hops -> final t3 in g_ha
    *(float4*)(v + 0) = tp[0]; *(float4*)(v + 4) = tp[1];
    *(float4*)(v + 8) = tp[2]; *(float4*)(v + 12) = tp[3];
    #pragma unroll
    for (int f = 0; f < 15; f++) v[f] = fmaxf(v[f], 0.f);
    for (int k = 0; k <= KHOP; k++) {
        float z = (k == 0) ? sb0 : 0.f;
        #pragma unroll
        for (int f = 0; f < 15; f++) z = fmaf(v[f], sW[k * 15 + f], z);
        g_z4[k * NN + n] = z;
    }
}

// ------------- layer 4 Horner hop (width 1) ---------------------------------
// mode: 0 -> told = g_z4[K], 1 -> told = g_t4a, 2 -> told = g_t4b
//       wout: 0 -> g_t4a, 1 -> g_t4b
__global__ void k_hop4(int mode, int wout, int kidx) {
    int n = blockIdx.x * blockDim.x + threadIdx.x;
    if (n >= NN) return;
    const float* told = (mode == 0) ? (g_z4 + KHOP * NN) : (mode == 1 ? g_t4a : g_t4b);
    float* tnew = wout ? g_t4b : g_t4a;
    const float* zk = g_z4 + kidx * NN;
    int s = g_off[n], e = g_off[n + 1];
    float sum = 0.f;
    int t = s;
    for (; t + 4 <= e; t += 4) {
        int2 a0 = g_csc[t], a1 = g_csc[t + 1], a2 = g_csc[t + 2], a3 = g_csc[t + 3];
        float v0 = __ldg(told + a0.x);
        float v1 = __ldg(told + a1.x);
        float v2 = __ldg(told + a2.x);
        float v3 = __ldg(told + a3.x);
        sum = fmaf(__int_as_float(a0.y), v0, sum);
        sum = fmaf(__int_as_float(a1.y), v1, sum);
        sum = fmaf(__int_as_float(a2.y), v2, sum);
        sum = fmaf(__int_as_float(a3.y), v3, sum);
    }
    for (; t < e; t++) {
        int2 a = g_csc[t];
        sum = fmaf(__int_as_float(a.y), __ldg(told + a.x), sum);
    }
    tnew[n] = zk[n] + sum;
}

__global__ void k_final(int which, float* __restrict__ out) {
    int n = blockIdx.x * blockDim.x + threadIdx.x;
    if (n < NN) out[n] = fmaxf(which ? g_t4b[n] : g_t4a[n], 0.f);
}

// ---------------- host launch ----------------
static inline int div_up(int a, int b) { return (a + b - 1) / b; }

extern "C" void kernel_launch(void* const* d_in, const int* in_sizes, int n_in,
                              void* d_out, int out_size) {
    const int*   ei = (const int*)d_in[0];
    const float* ew = (const float*)d_in[1];
    const float* c  = (const float*)d_in[2];
    const int*   ip = (const int*)d_in[3];
    const float* W1 = (const float*)d_in[4];
    const float* b1 = (const float*)d_in[5];
    const float* W2 = (const float*)d_in[6];
    const float* b2 = (const float*)d_in[7];
    const float* W3 = (const float*)d_in[8];
    const float* b3 = (const float*)d_in[9];
    const float* W4 = (const float*)d_in[10];
    const float* b4 = (const float*)d_in[11];
    float* out = (float*)d_out;

    int nb = div_up(NN, 256);
    int eb = div_up(EE, 256);

    // graph preprocessing
    k_zero<<<nb, 256>>>();
    k_degcnt<<<eb, 256>>>(ei, ew);
    k_dis<<<nb, 256>>>();
    k_bsum<<<NBLK_SCAN, SCAN_BS>>>();
    k_bscan<<<1, 128>>>();
    k_scan2<<<NBLK_SCAN, SCAN_BS>>>();
    k_scatter<<<eb, 256>>>(ei, ew);

    // layer 1: forward, acc1
    k_init1<<<nb, 256>>>(c, ip, W1, b1);
    int pp = 0;
    for (int k = 1; k <= KHOP; k++) {
        k_spmm1<<<nb, 256>>>(pp, W1 + k * 2 * 15);
        pp ^= 1;
    }

    // layer 2: forward, acc2
    k_trans12<<<nb, 256>>>(W2, b2);
    pp = 0;
    for (int k = 1; k <= KHOP; k++) {
        k_spmm2<<<div_up(NN, 64), 256>>>(pp, W2 + k * 450);
        pp ^= 1;
    }

    // layer 3: Horner, width 16 (final t3 lands in g_ha after 50 hops)
    k_trans23<<<nb, 256>>>(W3 + KHOP * 450);
    pp = 0;
    for (int k = KHOP - 1; k >= 0; k--) {
        k_hop3<<<div_up(NN, 64), 256>>>(pp, W3 + k * 450, (k == 0) ? 1 : 0, b3);
        pp ^= 1;
    }

    // layer 4: Horner, width 1 with precomputed z
    k_z4<<<nb, 256>>>(W4, b4);
    int mode = 0, w = 0;
    for (int k = KHOP - 1; k >= 0; k--) {
        k_hop4<<<nb, 256>>>(mode, w, k);
        mode = w ? 2 : 1;
        w ^= 1;
    }
    // 50 hops: last write went to (w^1) -> which buffer? track: final written = !w
    k_final<<<nb, 256>>>(w ? 0 : 1, out);
}